// round 1
// baseline (speedup 1.0000x reference)
#include <cuda_runtime.h>

// Mask2Former post-processing, fused:
//   out[b,c,H,W] = sum_q softmax(cls[b,q,:])[c] * sigmoid(bilinear4x(masks[b,q,:,:]))[H,W]
// B=8, Q=100, C=2 (of 3 logits), masks 128x128 -> 512x512, out fp32 [8,2,512,512].
//
// One block = one 64x64 output tile of one batch image. One thread = one input
// cell = 4x4 output pixels, needing a 3x3 input neighborhood. Per q: stage an
// 18x18 clamped input tile in smem, separable 2-tap lerps (phase weights
// 0.375/0.125), sigmoid, accumulate 2 class sums in registers.

#define Q       100
#define HI      128
#define WI      128
#define HO      512
#define WO      512
#define CELLS   16          // input cells per tile edge
#define SROWS   18          // input tile rows incl. halo
#define SPITCH  19          // padded pitch

__global__ __launch_bounds__(256)
void m2f_fused_kernel(const float* __restrict__ cls,    // [8,Q,3]
                      const float* __restrict__ masks,  // [8,Q,128,128]
                      float* __restrict__ out)          // [8,2,512,512]
{
    __shared__ float tile[SROWS * SPITCH];
    __shared__ float pc[Q][2];

    const int b   = blockIdx.z;
    const int tx  = blockIdx.x;           // 0..7
    const int ty  = blockIdx.y;           // 0..7
    const int tid = threadIdx.x;
    const int cx  = tid & 15;             // cell x within tile
    const int cy  = tid >> 4;             // cell y within tile

    // --- class softmax (keep classes 0,1 of 3) ---
    if (tid < Q) {
        const float* cl = cls + ((size_t)b * Q + tid) * 3;
        float a0 = cl[0], a1 = cl[1], a2 = cl[2];
        float mx = fmaxf(a0, fmaxf(a1, a2));
        float e0 = __expf(a0 - mx);
        float e1 = __expf(a1 - mx);
        float e2 = __expf(a2 - mx);
        float inv = __frcp_rn(e0 + e1 + e2);
        pc[tid][0] = e0 * inv;
        pc[tid][1] = e1 * inv;
    }

    const int iy0 = ty * CELLS;           // first input cell row of this tile
    const int ix0 = tx * CELLS;

    float acc[4][4][2];
    #pragma unroll
    for (int py = 0; py < 4; py++)
        #pragma unroll
        for (int px = 0; px < 4; px++) {
            acc[py][px][0] = 0.f;
            acc[py][px][1] = 0.f;
        }

    const float* mb = masks + (size_t)b * Q * HI * WI;

    for (int q = 0; q < Q; ++q) {
        __syncthreads();   // q=0: pc ready; q>0: prior tile consumed
        // stage 18x18 input tile with edge clamping (== jax renormalized border)
        const float* mq = mb + (size_t)q * HI * WI;
        #pragma unroll 2
        for (int i = tid; i < SROWS * SROWS; i += 256) {
            int r  = i / SROWS;
            int c  = i - r * SROWS;
            int gr = min(max(iy0 - 1 + r, 0), HI - 1);
            int gc = min(max(ix0 - 1 + c, 0), WI - 1);
            tile[r * SPITCH + c] = mq[gr * WI + gc];
        }
        __syncthreads();

        const float p0 = pc[q][0];
        const float p1 = pc[q][1];

        // 3x3 neighborhood of this thread's cell
        float v[3][3];
        #pragma unroll
        for (int j = 0; j < 3; j++)
            #pragma unroll
            for (int k = 0; k < 3; k++)
                v[j][k] = tile[(cy + j) * SPITCH + (cx + k)];

        // horizontal lerps: phases at -0.375,-0.125,+0.125,+0.375 around center col
        float hx[3][4];
        #pragma unroll
        for (int j = 0; j < 3; j++) {
            float m  = v[j][1];
            float dl = v[j][0] - m;
            float dr = v[j][2] - m;
            hx[j][0] = fmaf(0.375f, dl, m);
            hx[j][1] = fmaf(0.125f, dl, m);
            hx[j][2] = fmaf(0.125f, dr, m);
            hx[j][3] = fmaf(0.375f, dr, m);
        }

        // vertical lerps + sigmoid + accumulate
        #pragma unroll
        for (int px = 0; px < 4; px++) {
            float m  = hx[1][px];
            float dt = hx[0][px] - m;
            float db = hx[2][px] - m;
            float vv[4];
            vv[0] = fmaf(0.375f, dt, m);
            vv[1] = fmaf(0.125f, dt, m);
            vv[2] = fmaf(0.125f, db, m);
            vv[3] = fmaf(0.375f, db, m);
            #pragma unroll
            for (int py = 0; py < 4; py++) {
                float s = __frcp_rn(1.f + __expf(-vv[py]));
                acc[py][px][0] = fmaf(p0, s, acc[py][px][0]);
                acc[py][px][1] = fmaf(p1, s, acc[py][px][1]);
            }
        }
    }

    // --- write 4x4 block per class, float4 rows ---
    const int gy = (iy0 + cy) * 4;
    const int gx = (ix0 + cx) * 4;
    #pragma unroll
    for (int c = 0; c < 2; c++) {
        float* ob = out + (((size_t)(b * 2 + c) * HO + gy) * WO + gx);
        #pragma unroll
        for (int py = 0; py < 4; py++) {
            float4 val = make_float4(acc[py][0][c], acc[py][1][c],
                                     acc[py][2][c], acc[py][3][c]);
            *reinterpret_cast<float4*>(ob + py * WO) = val;
        }
    }
}

extern "C" void kernel_launch(void* const* d_in, const int* in_sizes, int n_in,
                              void* d_out, int out_size)
{
    // metadata order: class_queries_logits [8,100,3], masks_queries_logits [8,100,128,128]
    const float* cls   = (const float*)d_in[0];
    const float* masks = (const float*)d_in[1];
    if (n_in >= 2 && in_sizes[0] > in_sizes[1]) {   // defensive: swap if order differs
        const float* t = cls; cls = masks; masks = t;
    }
    float* out = (float*)d_out;

    dim3 grid(8, 8, 8);   // tiles_x, tiles_y, batch
    m2f_fused_kernel<<<grid, 256>>>(cls, masks, out);
}

// round 2
// speedup vs baseline: 2.7370x; 2.7370x over previous
#include <cuda_runtime.h>

// Mask2Former post-processing, fused:
//   out[b,c,H,W] = sum_q softmax(cls[b,q,:])[c] * sigmoid(bilinear4x(masks[b,q,:,:]))
// B=8, Q=100, C=2(of 3), masks 128x128 -> 512x512, out fp32 [8,2,512,512].
//
// sigmoid(x) = 0.5 + 0.5*tanh(x/2): the 0.5 scale is folded into the smem tile
// (interpolation is linear), the +0.5*sum(p) offset folded into the epilogue.
// One thread = one 128x128 input cell = 4x4 output px, 3x3 neighborhood.
// Double-buffered smem tile, 1 barrier per q, register prefetch of next tile.

#define Q       100
#define HI      128
#define WI      128
#define HO      512
#define WO      512
#define CELLS   16
#define SROWS   18
#define SPITCH  19
#define SELEMS  (SROWS * SROWS)   // 324

__device__ __forceinline__ float tanh_approx(float x) {
    float y;
    asm("tanh.approx.f32 %0, %1;" : "=f"(y) : "f"(x));
    return y;
}

__global__ __launch_bounds__(256, 4)
void m2f_fused_kernel(const float* __restrict__ cls,    // [8,Q,3]
                      const float* __restrict__ masks,  // [8,Q,128,128]
                      float* __restrict__ out)          // [8,2,512,512]
{
    __shared__ float tile[2][SROWS * SPITCH];
    __shared__ float pc[Q][2];

    const int b   = blockIdx.z;
    const int tx  = blockIdx.x;
    const int ty  = blockIdx.y;
    const int tid = threadIdx.x;
    const int cx  = tid & 15;
    const int cy  = tid >> 4;

    // --- class softmax (keep classes 0,1 of 3) ---
    if (tid < Q) {
        const float* cl = cls + ((size_t)b * Q + tid) * 3;
        float a0 = cl[0], a1 = cl[1], a2 = cl[2];
        float mx = fmaxf(a0, fmaxf(a1, a2));
        float e0 = __expf(a0 - mx);
        float e1 = __expf(a1 - mx);
        float e2 = __expf(a2 - mx);
        float inv = __frcp_rn(e0 + e1 + e2);
        pc[tid][0] = e0 * inv;
        pc[tid][1] = e1 * inv;
    }

    const int iy0 = ty * CELLS;
    const int ix0 = tx * CELLS;

    // --- q-invariant clamped fill offsets (324 elems, <=2 per thread) ---
    const int i0 = tid;
    const int r0 = i0 / SROWS, c0 = i0 - r0 * SROWS;
    const int s0 = r0 * SPITCH + c0;
    const int g0 = min(max(iy0 - 1 + r0, 0), HI - 1) * WI
                 + min(max(ix0 - 1 + c0, 0), WI - 1);
    const bool has1 = (tid + 256) < SELEMS;            // tid < 68
    const int i1 = tid + 256;
    const int r1 = i1 / SROWS, c1 = i1 - r1 * SROWS;
    const int s1 = r1 * SPITCH + c1;
    const int g1 = min(max(iy0 - 1 + r1, 0), HI - 1) * WI
                 + min(max(ix0 - 1 + c1, 0), WI - 1);

    const float* mq = masks + (size_t)b * Q * HI * WI;  // advances by HI*WI per q

    float acc[4][4][2];
    #pragma unroll
    for (int py = 0; py < 4; py++)
        #pragma unroll
        for (int px = 0; px < 4; px++) {
            acc[py][px][0] = 0.f;
            acc[py][px][1] = 0.f;
        }
    float P0 = 0.f, P1 = 0.f;

    // prefetch q=0 (0.5 folded in: tanh(x/2) argument)
    float f0 = 0.5f * __ldg(mq + g0);
    float f1 = has1 ? 0.5f * __ldg(mq + g1) : 0.f;
    tile[0][s0] = f0;
    if (has1) tile[0][s1] = f1;
    __syncthreads();

    #pragma unroll 2
    for (int q = 0; q < Q; ++q) {
        // prefetch next tile into registers (hides LDG under compute)
        if (q + 1 < Q) {
            const float* mn = mq + (size_t)(q + 1) * HI * WI;
            f0 = 0.5f * __ldg(mn + g0);
            if (has1) f1 = 0.5f * __ldg(mn + g1);
        }

        const float* cur = tile[q & 1];
        const float p0 = pc[q][0];
        const float p1 = pc[q][1];
        P0 += p0;
        P1 += p1;

        float v[3][3];
        #pragma unroll
        for (int j = 0; j < 3; j++)
            #pragma unroll
            for (int k = 0; k < 3; k++)
                v[j][k] = cur[(cy + j) * SPITCH + (cx + k)];

        float hx[3][4];
        #pragma unroll
        for (int j = 0; j < 3; j++) {
            float m  = v[j][1];
            float dl = v[j][0] - m;
            float dr = v[j][2] - m;
            hx[j][0] = fmaf(0.375f, dl, m);
            hx[j][1] = fmaf(0.125f, dl, m);
            hx[j][2] = fmaf(0.125f, dr, m);
            hx[j][3] = fmaf(0.375f, dr, m);
        }

        #pragma unroll
        for (int px = 0; px < 4; px++) {
            float m  = hx[1][px];
            float dt = hx[0][px] - m;
            float db = hx[2][px] - m;
            float t0 = tanh_approx(fmaf(0.375f, dt, m));
            float t1 = tanh_approx(fmaf(0.125f, dt, m));
            float t2 = tanh_approx(fmaf(0.125f, db, m));
            float t3 = tanh_approx(fmaf(0.375f, db, m));
            acc[0][px][0] = fmaf(p0, t0, acc[0][px][0]);
            acc[0][px][1] = fmaf(p1, t0, acc[0][px][1]);
            acc[1][px][0] = fmaf(p0, t1, acc[1][px][0]);
            acc[1][px][1] = fmaf(p1, t1, acc[1][px][1]);
            acc[2][px][0] = fmaf(p0, t2, acc[2][px][0]);
            acc[2][px][1] = fmaf(p1, t2, acc[2][px][1]);
            acc[3][px][0] = fmaf(p0, t3, acc[3][px][0]);
            acc[3][px][1] = fmaf(p1, t3, acc[3][px][1]);
        }

        // stage next tile into the other buffer; barrier publishes it
        if (q + 1 < Q) {
            float* nxt = tile[(q + 1) & 1];
            nxt[s0] = f0;
            if (has1) nxt[s1] = f1;
        }
        __syncthreads();
    }

    // --- epilogue: out = 0.5*(acc + P), float4 rows ---
    const int gy = (iy0 + cy) * 4;
    const int gx = (ix0 + cx) * 4;
    #pragma unroll
    for (int c = 0; c < 2; c++) {
        const float P = c ? P1 : P0;
        float* ob = out + (((size_t)(b * 2 + c) * HO + gy) * WO + gx);
        #pragma unroll
        for (int py = 0; py < 4; py++) {
            float4 val = make_float4(0.5f * (acc[py][0][c] + P),
                                     0.5f * (acc[py][1][c] + P),
                                     0.5f * (acc[py][2][c] + P),
                                     0.5f * (acc[py][3][c] + P));
            *reinterpret_cast<float4*>(ob + py * WO) = val;
        }
    }
}

extern "C" void kernel_launch(void* const* d_in, const int* in_sizes, int n_in,
                              void* d_out, int out_size)
{
    const float* cls   = (const float*)d_in[0];
    const float* masks = (const float*)d_in[1];
    if (n_in >= 2 && in_sizes[0] > in_sizes[1]) {
        const float* t = cls; cls = masks; masks = t;
    }
    float* out = (float*)d_out;

    dim3 grid(8, 8, 8);
    m2f_fused_kernel<<<grid, 256>>>(cls, masks, out);
}

// round 4
// speedup vs baseline: 2.8887x; 1.0554x over previous
#include <cuda_runtime.h>

// Mask2Former post-processing, fused (R3: no smem tile, no per-q barriers,
// packed f32x2 math, 1024 balanced CTAs):
//   out[b,c,H,W] = sum_q softmax(cls[b,q,:])[c] * sigmoid(bilinear4x(masks[b,q]))
// sigmoid(x) = 0.5 + 0.5*tanh(x/2); x/2 folded into a 0.5x at load, the
// +0.5*sum(p) offset folded into the epilogue.
// Thread = one input cell = 4x4 output px; loads its 3x3 clamped neighborhood
// straight from global (L1-resident), lerps in f32x2 pairs (px0,px3)/(px1,px2),
// 16 tanh.approx, class-weighted accumulate in packed pairs.

#define Q   100
#define HI  128
#define WI  128
#define HO  512
#define WO  512

using u64 = unsigned long long;

__device__ __forceinline__ u64 pk2(float lo, float hi) {
    u64 r; asm("mov.b64 %0, {%1, %2};" : "=l"(r) : "f"(lo), "f"(hi)); return r;
}
__device__ __forceinline__ void upk2(float& lo, float& hi, u64 p) {
    asm("mov.b64 {%0, %1}, %2;" : "=f"(lo), "=f"(hi) : "l"(p));
}
__device__ __forceinline__ u64 fma2(u64 a, u64 b, u64 c) {
    u64 d; asm("fma.rn.f32x2 %0, %1, %2, %3;" : "=l"(d) : "l"(a), "l"(b), "l"(c)); return d;
}
__device__ __forceinline__ u64 mul2(u64 a, u64 b) {
    u64 d; asm("mul.rn.f32x2 %0, %1, %2;" : "=l"(d) : "l"(a), "l"(b)); return d;
}
__device__ __forceinline__ u64 add2(u64 a, u64 b) {
    u64 d; asm("add.rn.f32x2 %0, %1, %2;" : "=l"(d) : "l"(a), "l"(b)); return d;
}
__device__ __forceinline__ float tanhap(float x) {
    float y; asm("tanh.approx.f32 %0, %1;" : "=f"(y) : "f"(x)); return y;
}

// packed lerp constants (both lanes identical)
#define C375 0x3EC000003EC00000ULL   // (0.375, 0.375)
#define C625 0x3F2000003F200000ULL   // (0.625, 0.625)
#define C125 0x3E0000003E000000ULL   // (0.125, 0.125)
#define C875 0x3F6000003F600000ULL   // (0.875, 0.875)

__global__ __launch_bounds__(128, 7)
void m2f_fused_kernel(const float* __restrict__ cls,    // [8,Q,3]
                      const float* __restrict__ masks,  // [8,Q,128,128]
                      float* __restrict__ out)          // [8,2,512,512]
{
    __shared__ float2 pc[Q];

    const int b    = blockIdx.z;
    const int tid  = threadIdx.x;
    const int lane = tid & 31;
    const int w    = tid >> 5;

    // --- class softmax (keep classes 0,1 of 3) ---
    if (tid < Q) {
        const float* cl = cls + ((size_t)b * Q + tid) * 3;
        float a0 = cl[0], a1 = cl[1], a2 = cl[2];
        float mx = fmaxf(a0, fmaxf(a1, a2));
        float e0 = __expf(a0 - mx);
        float e1 = __expf(a1 - mx);
        float e2 = __expf(a2 - mx);
        float inv = __frcp_rn(e0 + e1 + e2);
        pc[tid] = make_float2(e0 * inv, e1 * inv);
    }
    __syncthreads();

    // this thread's input cell
    const int gx = blockIdx.x * 32 + lane;   // 0..127
    const int gy = blockIdx.y * 4 + w;       // 0..127

    // q-invariant clamped 3x3 neighbor offsets
    const int xm = max(gx - 1, 0), xp = min(gx + 1, WI - 1);
    const int ym = max(gy - 1, 0), yp = min(gy + 1, HI - 1);
    const int r0 = ym * WI, r1 = gy * WI, r2 = yp * WI;
    int off[9];
    off[0] = r0 + xm; off[1] = r0 + gx; off[2] = r0 + xp;
    off[3] = r1 + xm; off[4] = r1 + gx; off[5] = r1 + xp;
    off[6] = r2 + xm; off[7] = r2 + gx; off[8] = r2 + xp;

    const float* mb = masks + (size_t)b * Q * HI * WI;

    // acc[py][pair][class]; pair0 = (px0,px3), pair1 = (px1,px2)
    u64 acc[4][2][2];
    #pragma unroll
    for (int py = 0; py < 4; py++)
        #pragma unroll
        for (int pr = 0; pr < 2; pr++) {
            acc[py][pr][0] = 0ULL;
            acc[py][pr][1] = 0ULL;
        }
    u64 Pp = 0ULL;   // (sum p0, sum p1)

    for (int q = 0; q < Q; ++q, mb += HI * WI) {
        // 3x3 neighborhood, pre-halved for tanh(x/2)
        float v[9];
        #pragma unroll
        for (int i = 0; i < 9; i++)
            v[i] = 0.5f * __ldg(mb + off[i]);

        const float2 p = pc[q];
        const u64 p00 = pk2(p.x, p.x);
        const u64 p11 = pk2(p.y, p.y);
        Pp = add2(Pp, pk2(p.x, p.y));

        // horizontal lerps: A[j]=(h@px0, h@px3), B[j]=(h@px1, h@px2)
        u64 A[3], B[3];
        #pragma unroll
        for (int j = 0; j < 3; j++) {
            const float m = v[j * 3 + 1];
            const u64 v02 = pk2(v[j * 3 + 0], v[j * 3 + 2]);
            const u64 mm  = pk2(m, m);
            const u64 m6  = mul2(C625, mm);
            const u64 m8  = mul2(C875, mm);
            A[j] = fma2(C375, v02, m6);
            B[j] = fma2(C125, v02, m8);
        }

        // vertical lerps + tanh + packed class accumulate
        #pragma unroll
        for (int pr = 0; pr < 2; pr++) {
            const u64 top = pr ? B[0] : A[0];
            const u64 mid = pr ? B[1] : A[1];
            const u64 bot = pr ? B[2] : A[2];
            const u64 m6 = mul2(C625, mid);
            const u64 m8 = mul2(C875, mid);
            u64 vv[4];
            vv[0] = fma2(C375, top, m6);
            vv[1] = fma2(C125, top, m8);
            vv[2] = fma2(C125, bot, m8);
            vv[3] = fma2(C375, bot, m6);
            #pragma unroll
            for (int py = 0; py < 4; py++) {
                float a, bb;
                upk2(a, bb, vv[py]);
                const u64 t = pk2(tanhap(a), tanhap(bb));
                acc[py][pr][0] = fma2(p00, t, acc[py][pr][0]);
                acc[py][pr][1] = fma2(p11, t, acc[py][pr][1]);
            }
        }
    }

    // --- epilogue: out = 0.5*(acc + P) ---
    float P0, P1;
    upk2(P0, P1, Pp);
    const int oy = gy * 4;
    const int ox = gx * 4;
    #pragma unroll
    for (int c = 0; c < 2; c++) {
        const float P = c ? P1 : P0;
        float* ob = out + (((size_t)(b * 2 + c) * HO + oy) * WO + ox);
        #pragma unroll
        for (int py = 0; py < 4; py++) {
            float x0, x3, x1, x2;
            upk2(x0, x3, acc[py][0][c]);
            upk2(x1, x2, acc[py][1][c]);
            float4 val = make_float4(0.5f * (x0 + P), 0.5f * (x1 + P),
                                     0.5f * (x2 + P), 0.5f * (x3 + P));
            *reinterpret_cast<float4*>(ob + py * WO) = val;
        }
    }
}

extern "C" void kernel_launch(void* const* d_in, const int* in_sizes, int n_in,
                              void* d_out, int out_size)
{
    const float* cls   = (const float*)d_in[0];
    const float* masks = (const float*)d_in[1];
    if (n_in >= 2 && in_sizes[0] > in_sizes[1]) {
        const float* t = cls; cls = masks; masks = t;
    }
    float* out = (float*)d_out;

    dim3 grid(4, 32, 8);   // x: 4x32 cells, y: 32x4 cell-rows, z: batch
    m2f_fused_kernel<<<grid, 128>>>(cls, masks, out);
}

// round 8
// speedup vs baseline: 3.1783x; 1.1002x over previous
#include <cuda_runtime.h>

// Mask2Former post-processing, fused (R4: half-cell threads for 2x warp
// parallelism; MUFU(tanh) is the binding pipe, keep it fed):
//   out[b,c,H,W] = sum_q softmax(cls[b,q,:])[c] * sigmoid(bilinear4x(masks[b,q]))
// sigmoid(x) = 0.5 + 0.5*tanh(x/2); the /2 is folded into the horizontal lerp
// weights, the +0.5*sum(p) offset folded into the epilogue.
// One thread = 4(wide) x 2(tall) output px of one input cell half: 2x3 input
// neighborhood (6 LDG, q-invariant clamped offsets), packed f32x2 lerps with
// pairing (px0,px3)/(px1,px2), 8 tanh.approx, packed class accumulate.

#define Q   100
#define HI  128
#define WI  128
#define HO  512
#define WO  512

using u64 = unsigned long long;

__device__ __forceinline__ u64 pk2(float lo, float hi) {
    u64 r; asm("mov.b64 %0, {%1, %2};" : "=l"(r) : "f"(lo), "f"(hi)); return r;
}
__device__ __forceinline__ void upk2(float& lo, float& hi, u64 p) {
    asm("mov.b64 {%0, %1}, %2;" : "=f"(lo), "=f"(hi) : "l"(p));
}
__device__ __forceinline__ u64 fma2(u64 a, u64 b, u64 c) {
    u64 d; asm("fma.rn.f32x2 %0, %1, %2, %3;" : "=l"(d) : "l"(a), "l"(b), "l"(c)); return d;
}
__device__ __forceinline__ u64 mul2(u64 a, u64 b) {
    u64 d; asm("mul.rn.f32x2 %0, %1, %2;" : "=l"(d) : "l"(a), "l"(b)); return d;
}
__device__ __forceinline__ u64 add2(u64 a, u64 b) {
    u64 d; asm("add.rn.f32x2 %0, %1, %2;" : "=l"(d) : "l"(a), "l"(b)); return d;
}
__device__ __forceinline__ float tanhap(float x) {
    float y; asm("tanh.approx.f32 %0, %1;" : "=f"(y) : "f"(x)); return y;
}

// horizontal lerp weights with the 0.5 (tanh(x/2)) folded in:
// 0.5*0.375=0.1875, 0.5*0.625=0.3125, 0.5*0.125=0.0625, 0.5*0.875=0.4375
#define C1875 0x3E4000003E400000ULL
#define C3125 0x3EA000003EA00000ULL
#define C0625 0x3D8000003D800000ULL
#define C4375 0x3EE000003EE00000ULL

__global__ __launch_bounds__(128, 9)
void m2f_fused_kernel(const float* __restrict__ cls,    // [8,Q,3]
                      const float* __restrict__ masks,  // [8,Q,128,128]
                      float* __restrict__ out)          // [8,2,512,512]
{
    __shared__ float2 pc[Q];

    const int b    = blockIdx.z;
    const int tid  = threadIdx.x;
    const int lane = tid & 31;
    const int w    = tid >> 5;

    // --- class softmax (keep classes 0,1 of 3) ---
    if (tid < Q) {
        const float* cl = cls + ((size_t)b * Q + tid) * 3;
        float a0 = cl[0], a1 = cl[1], a2 = cl[2];
        float mx = fmaxf(a0, fmaxf(a1, a2));
        float e0 = __expf(a0 - mx);
        float e1 = __expf(a1 - mx);
        float e2 = __expf(a2 - mx);
        float inv = __frcp_rn(e0 + e1 + e2);
        pc[tid] = make_float2(e0 * inv, e1 * inv);
    }
    __syncthreads();

    // this thread's input cell and half (h=0: top 2 output rows, h=1: bottom 2)
    const int gx = blockIdx.x * 32 + lane;          // 0..127
    const int gy = blockIdx.y * 2 + (w >> 1);       // 0..127
    const int h  = w & 1;

    // q-invariant clamped offsets: far row + center row, 3 cols each
    const int xm = max(gx - 1, 0), xp = min(gx + 1, WI - 1);
    const int yf = h ? min(gy + 1, HI - 1) : max(gy - 1, 0);
    const int rF = yf * WI, rC = gy * WI;
    const int oF0 = rF + xm, oF1 = rF + gx, oF2 = rF + xp;
    const int oC0 = rC + xm, oC1 = rC + gx, oC2 = rC + xp;

    // vertical weights per output row (r=0,1), order depends on half:
    // top:    row0 = 0.375*far + 0.625*ctr ; row1 = 0.125*far + 0.875*ctr
    // bottom: row0 = 0.125*far + 0.875*ctr ; row1 = 0.375*far + 0.625*ctr
    const float wf0 = h ? 0.125f : 0.375f;
    const float wf1 = h ? 0.375f : 0.125f;
    const u64 WF0 = pk2(wf0, wf0), WC0 = pk2(1.f - wf0, 1.f - wf0);
    const u64 WF1 = pk2(wf1, wf1), WC1 = pk2(1.f - wf1, 1.f - wf1);

    const float* mb = masks + (size_t)b * Q * HI * WI;

    // acc[row][pair][class]; pair0 = (px0,px3), pair1 = (px1,px2)
    u64 acc[2][2][2];
    #pragma unroll
    for (int r = 0; r < 2; r++)
        #pragma unroll
        for (int pr = 0; pr < 2; pr++) {
            acc[r][pr][0] = 0ULL;
            acc[r][pr][1] = 0ULL;
        }
    u64 Pp = 0ULL;   // (sum p0, sum p1)

    #pragma unroll 2
    for (int q = 0; q < Q; ++q, mb += HI * WI) {
        // 2x3 neighborhood
        const float fl = __ldg(mb + oF0), fm = __ldg(mb + oF1), fr = __ldg(mb + oF2);
        const float cl2 = __ldg(mb + oC0), cm = __ldg(mb + oC1), cr = __ldg(mb + oC2);

        const float2 p = pc[q];
        const u64 p00 = pk2(p.x, p.x);
        const u64 p11 = pk2(p.y, p.y);
        Pp = add2(Pp, pk2(p.x, p.y));

        // horizontal lerps (0.5 folded): A=(h@px0,h@px3), B=(h@px1,h@px2)
        const u64 fLR = pk2(fl, fr), fMM = pk2(fm, fm);
        const u64 cLR = pk2(cl2, cr), cMM = pk2(cm, cm);
        const u64 FA = fma2(C1875, fLR, mul2(C3125, fMM));
        const u64 FB = fma2(C0625, fLR, mul2(C4375, fMM));
        const u64 CA = fma2(C1875, cLR, mul2(C3125, cMM));
        const u64 CB = fma2(C0625, cLR, mul2(C4375, cMM));

        // vertical lerps + tanh + packed class accumulate
        #pragma unroll
        for (int pr = 0; pr < 2; pr++) {
            const u64 T = pr ? FB : FA;     // far row
            const u64 C = pr ? CB : CA;     // center row
            const u64 v0 = fma2(WF0, T, mul2(WC0, C));
            const u64 v1 = fma2(WF1, T, mul2(WC1, C));
            float a, bb;
            upk2(a, bb, v0);
            const u64 t0 = pk2(tanhap(a), tanhap(bb));
            upk2(a, bb, v1);
            const u64 t1 = pk2(tanhap(a), tanhap(bb));
            acc[0][pr][0] = fma2(p00, t0, acc[0][pr][0]);
            acc[0][pr][1] = fma2(p11, t0, acc[0][pr][1]);
            acc[1][pr][0] = fma2(p00, t1, acc[1][pr][0]);
            acc[1][pr][1] = fma2(p11, t1, acc[1][pr][1]);
        }
    }

    // --- epilogue: out = 0.5*(acc + P) ---
    float P0, P1;
    upk2(P0, P1, Pp);
    const int oy = gy * 4 + h * 2;
    const int ox = gx * 4;
    #pragma unroll
    for (int c = 0; c < 2; c++) {
        const float P = c ? P1 : P0;
        float* ob = out + (((size_t)(b * 2 + c) * HO + oy) * WO + ox);
        #pragma unroll
        for (int r = 0; r < 2; r++) {
            float x0, x3, x1, x2;
            upk2(x0, x3, acc[r][0][c]);
            upk2(x1, x2, acc[r][1][c]);
            float4 val = make_float4(0.5f * (x0 + P), 0.5f * (x1 + P),
                                     0.5f * (x2 + P), 0.5f * (x3 + P));
            *reinterpret_cast<float4*>(ob + r * WO) = val;
        }
    }
}

extern "C" void kernel_launch(void* const* d_in, const int* in_sizes, int n_in,
                              void* d_out, int out_size)
{
    const float* cls   = (const float*)d_in[0];
    const float* masks = (const float*)d_in[1];
    if (n_in >= 2 && in_sizes[0] > in_sizes[1]) {
        const float* t = cls; cls = masks; masks = t;
    }
    float* out = (float*)d_out;

    dim3 grid(4, 64, 8);   // x: 4 groups of 32 cells; y: 64 (2 cell-rows/block); z: batch
    m2f_fused_kernel<<<grid, 128>>>(cls, masks, out);
}